// round 1
// baseline (speedup 1.0000x reference)
#include <cuda_runtime.h>
#include <math.h>

// Problem constants (fixed by reference)
#define D_IN   512
#define D_K    256
#define NSLOT  64
#define TILE_R 64
#define KT     32
#define NTH    256

// Shared-memory strides (floats). All ≡ 0 mod 4 (float4 align) and chosen so
// LDS.128 reads at col 4*lane are bank-conflict-free (stride ≡ 4 mod 32).
#define MS_ST 260   // memory bank [64 slots][256]
#define ES_ST 260   // encoded tile (reused for memory-read tile) [64][256]
#define AS_ST 68    // attention tile [64][64]
#define XS_ST 65    // X chunk, transposed [32 k][64 rows]
#define WS_ST 260   // weight chunk, transposed [32 k][256 cols]

#define SMEM_FLOATS (NSLOT*MS_ST + TILE_R*ES_ST + TILE_R*AS_ST + KT*XS_ST + KT*WS_ST)
#define SMEM_BYTES  (SMEM_FLOATS * 4)

__global__ __launch_bounds__(NTH, 1)
void mwm_fused(const float* __restrict__ seq,
               const float* __restrict__ enc_w,
               const float* __restrict__ enc_b,
               const float* __restrict__ memw,
               const float* __restrict__ dec_w,
               const float* __restrict__ dec_b,
               float* __restrict__ recon,
               float* __restrict__ att,
               float* __restrict__ memout)
{
    extern __shared__ float sm[];
    float* memS = sm;                       // [64][MS_ST]
    float* eS   = memS + NSLOT * MS_ST;     // [64][ES_ST]  encoded, later memory-read
    float* aS   = eS   + TILE_R * ES_ST;    // [64][AS_ST]  attention
    float* Xs   = aS   + TILE_R * AS_ST;    // [KT][XS_ST]  x chunk (transposed)
    float* Ws   = Xs   + KT * XS_ST;        // [KT][WS_ST]  weight chunk (transposed)

    const int tid = threadIdx.x;
    const int wi  = tid >> 5;          // 0..7  -> row block
    const int ln  = tid & 31;          // 0..31 -> col block
    const int r0  = wi * 8;            // 8 rows per thread
    const int cA  = ln * 4;            // cols [cA..cA+3]
    const int cB  = 128 + ln * 4;      // cols [cB..cB+3]
    const long row0 = (long)blockIdx.x * TILE_R;

    // ---- Load memory bank into smem: memS[slot][k] ----
    #pragma unroll 4
    for (int idx = tid; idx < NSLOT * (D_K / 4); idx += NTH) {
        int slot = idx >> 6;
        int c4   = (idx & 63) << 2;
        float4 v = *(const float4*)(memw + slot * D_K + c4);
        *(float4*)(memS + slot * MS_ST + c4) = v;
    }

    // ================= GEMM1: e = tanh(x @ enc_w^T + enc_b) =================
    float acc[8][8];
    #pragma unroll
    for (int a = 0; a < 8; a++)
        #pragma unroll
        for (int b = 0; b < 8; b++) acc[a][b] = 0.f;

    for (int kt = 0; kt < D_IN / KT; kt++) {
        __syncthreads();
        // X chunk: seq[row0+row][kt*32 + k] -> Xs[k][row]
        #pragma unroll 2
        for (int idx = tid; idx < (TILE_R * KT / 4); idx += NTH) {
            int row = idx >> 3;
            int kq  = idx & 7;
            float4 v = *(const float4*)(seq + (row0 + row) * D_IN + kt * KT + (kq << 2));
            Xs[(kq * 4 + 0) * XS_ST + row] = v.x;
            Xs[(kq * 4 + 1) * XS_ST + row] = v.y;
            Xs[(kq * 4 + 2) * XS_ST + row] = v.z;
            Xs[(kq * 4 + 3) * XS_ST + row] = v.w;
        }
        // W chunk: enc_w[c][kt*32 + k] -> Ws[k][c]
        #pragma unroll 8
        for (int idx = tid; idx < (D_K * KT / 4); idx += NTH) {
            int c  = idx >> 3;
            int kq = idx & 7;
            float4 v = *(const float4*)(enc_w + c * D_IN + kt * KT + (kq << 2));
            Ws[(kq * 4 + 0) * WS_ST + c] = v.x;
            Ws[(kq * 4 + 1) * WS_ST + c] = v.y;
            Ws[(kq * 4 + 2) * WS_ST + c] = v.z;
            Ws[(kq * 4 + 3) * WS_ST + c] = v.w;
        }
        __syncthreads();
        #pragma unroll 4
        for (int kk = 0; kk < KT; kk++) {
            float4 b0 = *(const float4*)(Ws + kk * WS_ST + cA);
            float4 b1 = *(const float4*)(Ws + kk * WS_ST + cB);
            #pragma unroll
            for (int rr = 0; rr < 8; rr++) {
                float a = Xs[kk * XS_ST + r0 + rr];
                acc[rr][0] += a * b0.x; acc[rr][1] += a * b0.y;
                acc[rr][2] += a * b0.z; acc[rr][3] += a * b0.w;
                acc[rr][4] += a * b1.x; acc[rr][5] += a * b1.y;
                acc[rr][6] += a * b1.z; acc[rr][7] += a * b1.w;
            }
        }
    }

    // bias + tanh -> eS
    {
        float4 eb0 = *(const float4*)(enc_b + cA);
        float4 eb1 = *(const float4*)(enc_b + cB);
        #pragma unroll
        for (int rr = 0; rr < 8; rr++) {
            float4 v0, v1;
            v0.x = tanhf(acc[rr][0] + eb0.x);
            v0.y = tanhf(acc[rr][1] + eb0.y);
            v0.z = tanhf(acc[rr][2] + eb0.z);
            v0.w = tanhf(acc[rr][3] + eb0.w);
            v1.x = tanhf(acc[rr][4] + eb1.x);
            v1.y = tanhf(acc[rr][5] + eb1.y);
            v1.z = tanhf(acc[rr][6] + eb1.z);
            v1.w = tanhf(acc[rr][7] + eb1.w);
            *(float4*)(eS + (r0 + rr) * ES_ST + cA) = v0;
            *(float4*)(eS + (r0 + rr) * ES_ST + cB) = v1;
        }
    }
    __syncthreads();

    // ========== GEMM2: logits[r][m] = sum_k e[r][k] * mem[m][k] ==========
    // thread owns rows r0..r0+7, slots {ln, ln+32}
    float l0[8], l1[8];
    #pragma unroll
    for (int rr = 0; rr < 8; rr++) { l0[rr] = 0.f; l1[rr] = 0.f; }
    #pragma unroll 2
    for (int k = 0; k < D_K; k += 4) {
        float4 b0 = *(const float4*)(memS + ln * MS_ST + k);
        float4 b1 = *(const float4*)(memS + (ln + 32) * MS_ST + k);
        #pragma unroll
        for (int rr = 0; rr < 8; rr++) {
            float4 a = *(const float4*)(eS + (r0 + rr) * ES_ST + k);
            l0[rr] += a.x * b0.x + a.y * b0.y + a.z * b0.z + a.w * b0.w;
            l1[rr] += a.x * b1.x + a.y * b1.y + a.z * b1.z + a.w * b1.w;
        }
    }

    // ---- softmax over 64 slots (scale 1/sqrt(256) = 1/16), row in one warp ----
    const float sc = 0.0625f;
    #pragma unroll
    for (int rr = 0; rr < 8; rr++) {
        float m = fmaxf(l0[rr], l1[rr]);
        #pragma unroll
        for (int o = 16; o > 0; o >>= 1)
            m = fmaxf(m, __shfl_xor_sync(0xffffffffu, m, o));
        float e0 = __expf((l0[rr] - m) * sc);
        float e1 = __expf((l1[rr] - m) * sc);
        float s = e0 + e1;
        #pragma unroll
        for (int o = 16; o > 0; o >>= 1)
            s += __shfl_xor_sync(0xffffffffu, s, o);
        float inv = 1.0f / s;
        aS[(r0 + rr) * AS_ST + ln]      = e0 * inv;
        aS[(r0 + rr) * AS_ST + ln + 32] = e1 * inv;
    }
    __syncthreads();   // aS ready; also: everyone is past GEMM2 -> eS reusable

    // ---- write attention output (coalesced) ----
    #pragma unroll 4
    for (int idx = tid; idx < TILE_R * NSLOT / 4; idx += NTH) {
        int row = idx >> 4;
        int c4  = (idx & 15) << 2;
        float4 v = *(const float4*)(aS + row * AS_ST + c4);
        *(float4*)(att + (row0 + row) * NSLOT + c4) = v;
    }

    // ========== GEMM3: m[r][c] = sum_s a[r][s] * mem[s][c] ==========
    float m3[8][8];
    #pragma unroll
    for (int a = 0; a < 8; a++)
        #pragma unroll
        for (int b = 0; b < 8; b++) m3[a][b] = 0.f;
    #pragma unroll 4
    for (int k = 0; k < NSLOT; k++) {
        float4 b0 = *(const float4*)(memS + k * MS_ST + cA);
        float4 b1 = *(const float4*)(memS + k * MS_ST + cB);
        #pragma unroll
        for (int rr = 0; rr < 8; rr++) {
            float a = aS[(r0 + rr) * AS_ST + k];
            m3[rr][0] += a * b0.x; m3[rr][1] += a * b0.y;
            m3[rr][2] += a * b0.z; m3[rr][3] += a * b0.w;
            m3[rr][4] += a * b1.x; m3[rr][5] += a * b1.y;
            m3[rr][6] += a * b1.z; m3[rr][7] += a * b1.w;
        }
    }

    // store memory-read tile: to gmem output and to eS (reused as m operand)
    #pragma unroll
    for (int rr = 0; rr < 8; rr++) {
        float4 v0 = make_float4(m3[rr][0], m3[rr][1], m3[rr][2], m3[rr][3]);
        float4 v1 = make_float4(m3[rr][4], m3[rr][5], m3[rr][6], m3[rr][7]);
        *(float4*)(eS + (r0 + rr) * ES_ST + cA) = v0;
        *(float4*)(eS + (r0 + rr) * ES_ST + cB) = v1;
        *(float4*)(memout + (row0 + r0 + rr) * D_K + cA) = v0;
        *(float4*)(memout + (row0 + r0 + rr) * D_K + cB) = v1;
    }

    // ========== GEMM4: recon[r][d] = sum_k m[r][k] * dec_w[d][k] + dec_b[d] ==========
    for (int h = 0; h < 2; h++) {          // two 256-wide output halves
        float a4[8][8];
        #pragma unroll
        for (int a = 0; a < 8; a++)
            #pragma unroll
            for (int b = 0; b < 8; b++) a4[a][b] = 0.f;

        for (int kt = 0; kt < D_K / KT; kt++) {
            __syncthreads();   // protects Ws reuse (and, on first iter, eS writes)
            #pragma unroll 8
            for (int idx = tid; idx < (256 * KT / 4); idx += NTH) {
                int c  = idx >> 3;
                int kq = idx & 7;
                float4 v = *(const float4*)(dec_w + (h * 256 + c) * D_K + kt * KT + (kq << 2));
                Ws[(kq * 4 + 0) * WS_ST + c] = v.x;
                Ws[(kq * 4 + 1) * WS_ST + c] = v.y;
                Ws[(kq * 4 + 2) * WS_ST + c] = v.z;
                Ws[(kq * 4 + 3) * WS_ST + c] = v.w;
            }
            __syncthreads();
            #pragma unroll 4
            for (int kk = 0; kk < KT; kk++) {
                float4 b0 = *(const float4*)(Ws + kk * WS_ST + cA);
                float4 b1 = *(const float4*)(Ws + kk * WS_ST + cB);
                #pragma unroll
                for (int rr = 0; rr < 8; rr++) {
                    float a = eS[(r0 + rr) * ES_ST + kt * KT + kk];
                    a4[rr][0] += a * b0.x; a4[rr][1] += a * b0.y;
                    a4[rr][2] += a * b0.z; a4[rr][3] += a * b0.w;
                    a4[rr][4] += a * b1.x; a4[rr][5] += a * b1.y;
                    a4[rr][6] += a * b1.z; a4[rr][7] += a * b1.w;
                }
            }
        }

        float4 db0 = *(const float4*)(dec_b + h * 256 + cA);
        float4 db1 = *(const float4*)(dec_b + h * 256 + cB);
        #pragma unroll
        for (int rr = 0; rr < 8; rr++) {
            float4 v0 = make_float4(a4[rr][0] + db0.x, a4[rr][1] + db0.y,
                                    a4[rr][2] + db0.z, a4[rr][3] + db0.w);
            float4 v1 = make_float4(a4[rr][4] + db1.x, a4[rr][5] + db1.y,
                                    a4[rr][6] + db1.z, a4[rr][7] + db1.w);
            *(float4*)(recon + (row0 + r0 + rr) * D_IN + h * 256 + cA) = v0;
            *(float4*)(recon + (row0 + r0 + rr) * D_IN + h * 256 + cB) = v1;
        }
    }
}

extern "C" void kernel_launch(void* const* d_in, const int* in_sizes, int n_in,
                              void* d_out, int out_size)
{
    const float* seq   = (const float*)d_in[0];
    const float* enc_w = (const float*)d_in[1];
    const float* enc_b = (const float*)d_in[2];
    const float* memw  = (const float*)d_in[3];
    const float* dec_w = (const float*)d_in[4];
    const float* dec_b = (const float*)d_in[5];

    const long R = (long)in_sizes[0] / D_IN;   // total rows = B*S = 65536

    float* out    = (float*)d_out;
    float* recon  = out;                        // [R, 512]
    float* att    = out + R * D_IN;             // [R, 64]
    float* memout = att + R * NSLOT;            // [R, 256]

    cudaFuncSetAttribute(mwm_fused, cudaFuncAttributeMaxDynamicSharedMemorySize, SMEM_BYTES);

    dim3 grid((unsigned)(R / TILE_R));
    mwm_fused<<<grid, NTH, SMEM_BYTES>>>(seq, enc_w, enc_b, memw, dec_w, dec_b,
                                         recon, att, memout);
}

// round 2
// speedup vs baseline: 1.0246x; 1.0246x over previous
#include <cuda_runtime.h>
#include <math.h>

// Problem constants (fixed by reference)
#define D_IN   512
#define D_K    256
#define NSLOT  64
#define TILE_R 64
#define KT     32
#define NTH    256

// Shared-memory strides (floats). Chosen so vector LDS are bank-conflict-free
// (stride ≡ 4 mod 32 for the 260 ones) and 8B-aligned pair loads work (even).
#define MS_ST 260   // memory bank [64 slots][256]
#define ES_ST 260   // encoded tile (reused for memory-read tile) [64][256]
#define AS_ST 68    // attention tile [64][64]
#define XS_ST 66    // X chunk, transposed [32 k][64 rows]  (even: pair loads)
#define WS_ST 260   // weight chunk, transposed [32 k][256 cols]

#define SMEM_FLOATS (NSLOT*MS_ST + TILE_R*ES_ST + TILE_R*AS_ST + KT*XS_ST + KT*WS_ST)
#define SMEM_BYTES  (SMEM_FLOATS * 4)

typedef unsigned long long ull;

// Packed fp32x2 FMA (Blackwell): 2 MACs per issue slot, fp32-exact per element.
__device__ __forceinline__ void fma2(ull &d, ull a, ull b) {
    asm("fma.rn.f32x2 %0, %1, %2, %0;" : "+l"(d) : "l"(a), "l"(b));
}
__device__ __forceinline__ ull pack2(float x, float y) {
    ull r;
    asm("mov.b64 %0, {%1, %2};" : "=l"(r)
        : "r"(__float_as_uint(x)), "r"(__float_as_uint(y)));
    return r;
}
__device__ __forceinline__ float2 unpack2(ull v) {
    unsigned lo, hi;
    asm("mov.b64 {%0, %1}, %2;" : "=r"(lo), "=r"(hi) : "l"(v));
    return make_float2(__uint_as_float(lo), __uint_as_float(hi));
}

__global__ __launch_bounds__(NTH, 1)
void mwm_fused(const float* __restrict__ seq,
               const float* __restrict__ enc_w,
               const float* __restrict__ enc_b,
               const float* __restrict__ memw,
               const float* __restrict__ dec_w,
               const float* __restrict__ dec_b,
               float* __restrict__ recon,
               float* __restrict__ att,
               float* __restrict__ memout)
{
    extern __shared__ float sm[];
    float* memS = sm;                       // [64][MS_ST]
    float* eS   = memS + NSLOT * MS_ST;     // [64][ES_ST]  encoded, later memory-read
    float* aS   = eS   + TILE_R * ES_ST;    // [64][AS_ST]  attention
    float* Xs   = aS   + TILE_R * AS_ST;    // [KT][XS_ST]  x chunk (transposed)
    float* Ws   = Xs   + KT * XS_ST;        // [KT][WS_ST]  weight chunk (transposed)

    const int tid = threadIdx.x;
    const int wi  = tid >> 5;          // 0..7  -> row block
    const int ln  = tid & 31;          // 0..31 -> col block
    const int r0  = wi * 8;            // 8 rows per thread
    const int cA  = ln * 4;            // cols [cA..cA+3]
    const int cB  = 128 + ln * 4;      // cols [cB..cB+3]
    const long row0 = (long)blockIdx.x * TILE_R;

    // ---- Load memory bank into smem: memS[slot][k] ----
    #pragma unroll 4
    for (int idx = tid; idx < NSLOT * (D_K / 4); idx += NTH) {
        int slot = idx >> 6;
        int c4   = (idx & 63) << 2;
        float4 v = *(const float4*)(memw + slot * D_K + c4);
        *(float4*)(memS + slot * MS_ST + c4) = v;
    }

    // ================= GEMM1: e = tanh(x @ enc_w^T + enc_b) =================
    // Accumulators packed over ROW PAIRS: acc2[p][c] = {row r0+2p, row r0+2p+1}
    ull acc2[4][8];
    #pragma unroll
    for (int p = 0; p < 4; p++)
        #pragma unroll
        for (int c = 0; c < 8; c++) acc2[p][c] = 0ull;

    for (int kt = 0; kt < D_IN / KT; kt++) {
        __syncthreads();
        // X chunk: seq[row0+row][kt*32 + k] -> Xs[k][row]
        #pragma unroll 2
        for (int idx = tid; idx < (TILE_R * KT / 4); idx += NTH) {
            int row = idx >> 3;
            int kq  = idx & 7;
            float4 v = *(const float4*)(seq + (row0 + row) * D_IN + kt * KT + (kq << 2));
            Xs[(kq * 4 + 0) * XS_ST + row] = v.x;
            Xs[(kq * 4 + 1) * XS_ST + row] = v.y;
            Xs[(kq * 4 + 2) * XS_ST + row] = v.z;
            Xs[(kq * 4 + 3) * XS_ST + row] = v.w;
        }
        // W chunk: enc_w[c][kt*32 + k] -> Ws[k][c]
        #pragma unroll 8
        for (int idx = tid; idx < (D_K * KT / 4); idx += NTH) {
            int c  = idx >> 3;
            int kq = idx & 7;
            float4 v = *(const float4*)(enc_w + c * D_IN + kt * KT + (kq << 2));
            Ws[(kq * 4 + 0) * WS_ST + c] = v.x;
            Ws[(kq * 4 + 1) * WS_ST + c] = v.y;
            Ws[(kq * 4 + 2) * WS_ST + c] = v.z;
            Ws[(kq * 4 + 3) * WS_ST + c] = v.w;
        }
        __syncthreads();
        #pragma unroll 4
        for (int kk = 0; kk < KT; kk++) {
            const float* wrow = Ws + kk * WS_ST;
            float4 b0 = *(const float4*)(wrow + cA);
            float4 b1 = *(const float4*)(wrow + cB);
            ull bb[8];
            bb[0] = pack2(b0.x, b0.x); bb[1] = pack2(b0.y, b0.y);
            bb[2] = pack2(b0.z, b0.z); bb[3] = pack2(b0.w, b0.w);
            bb[4] = pack2(b1.x, b1.x); bb[5] = pack2(b1.y, b1.y);
            bb[6] = pack2(b1.z, b1.z); bb[7] = pack2(b1.w, b1.w);
            const float* xrow = Xs + kk * XS_ST + r0;
            ull aa[4];
            aa[0] = *(const ull*)(xrow + 0);
            aa[1] = *(const ull*)(xrow + 2);
            aa[2] = *(const ull*)(xrow + 4);
            aa[3] = *(const ull*)(xrow + 6);
            #pragma unroll
            for (int p = 0; p < 4; p++)
                #pragma unroll
                for (int c = 0; c < 8; c++)
                    fma2(acc2[p][c], aa[p], bb[c]);
        }
    }

    // bias + tanh -> eS (row r0+2p from .x lane, row r0+2p+1 from .y lane)
    {
        float4 eb0 = *(const float4*)(enc_b + cA);
        float4 eb1 = *(const float4*)(enc_b + cB);
        #pragma unroll
        for (int p = 0; p < 4; p++) {
            float2 u[8];
            #pragma unroll
            for (int c = 0; c < 8; c++) u[c] = unpack2(acc2[p][c]);
            float4 vA0, vB0, vA1, vB1;
            vA0.x = tanhf(u[0].x + eb0.x); vA0.y = tanhf(u[1].x + eb0.y);
            vA0.z = tanhf(u[2].x + eb0.z); vA0.w = tanhf(u[3].x + eb0.w);
            vB0.x = tanhf(u[4].x + eb1.x); vB0.y = tanhf(u[5].x + eb1.y);
            vB0.z = tanhf(u[6].x + eb1.z); vB0.w = tanhf(u[7].x + eb1.w);
            vA1.x = tanhf(u[0].y + eb0.x); vA1.y = tanhf(u[1].y + eb0.y);
            vA1.z = tanhf(u[2].y + eb0.z); vA1.w = tanhf(u[3].y + eb0.w);
            vB1.x = tanhf(u[4].y + eb1.x); vB1.y = tanhf(u[5].y + eb1.y);
            vB1.z = tanhf(u[6].y + eb1.z); vB1.w = tanhf(u[7].y + eb1.w);
            *(float4*)(eS + (r0 + 2*p    ) * ES_ST + cA) = vA0;
            *(float4*)(eS + (r0 + 2*p    ) * ES_ST + cB) = vB0;
            *(float4*)(eS + (r0 + 2*p + 1) * ES_ST + cA) = vA1;
            *(float4*)(eS + (r0 + 2*p + 1) * ES_ST + cB) = vB1;
        }
    }
    __syncthreads();

    // ========== GEMM2: logits[r][m] = sum_k e[r][k] * mem[m][k] ==========
    // Packed over k: two half dot-products per register pair, horizontal add at end.
    ull L0[8], L1[8];
    #pragma unroll
    for (int rr = 0; rr < 8; rr++) { L0[rr] = 0ull; L1[rr] = 0ull; }
    #pragma unroll 2
    for (int k = 0; k < D_K; k += 4) {
        ulonglong2 bm0 = *(const ulonglong2*)(memS + ln * MS_ST + k);
        ulonglong2 bm1 = *(const ulonglong2*)(memS + (ln + 32) * MS_ST + k);
        #pragma unroll
        for (int rr = 0; rr < 8; rr++) {
            ulonglong2 av = *(const ulonglong2*)(eS + (r0 + rr) * ES_ST + k);
            fma2(L0[rr], av.x, bm0.x); fma2(L0[rr], av.y, bm0.y);
            fma2(L1[rr], av.x, bm1.x); fma2(L1[rr], av.y, bm1.y);
        }
    }
    float l0[8], l1[8];
    #pragma unroll
    for (int rr = 0; rr < 8; rr++) {
        float2 a = unpack2(L0[rr]); l0[rr] = a.x + a.y;
        float2 b = unpack2(L1[rr]); l1[rr] = b.x + b.y;
    }

    // ---- softmax over 64 slots (scale 1/sqrt(256) = 1/16), row in one warp ----
    const float sc = 0.0625f;
    #pragma unroll
    for (int rr = 0; rr < 8; rr++) {
        float m = fmaxf(l0[rr], l1[rr]);
        #pragma unroll
        for (int o = 16; o > 0; o >>= 1)
            m = fmaxf(m, __shfl_xor_sync(0xffffffffu, m, o));
        float e0 = __expf((l0[rr] - m) * sc);
        float e1 = __expf((l1[rr] - m) * sc);
        float s = e0 + e1;
        #pragma unroll
        for (int o = 16; o > 0; o >>= 1)
            s += __shfl_xor_sync(0xffffffffu, s, o);
        float inv = 1.0f / s;
        aS[(r0 + rr) * AS_ST + ln]      = e0 * inv;
        aS[(r0 + rr) * AS_ST + ln + 32] = e1 * inv;
    }
    __syncthreads();   // aS ready; also: everyone is past GEMM2 -> eS reusable

    // ---- write attention output (coalesced) ----
    #pragma unroll 4
    for (int idx = tid; idx < TILE_R * NSLOT / 4; idx += NTH) {
        int row = idx >> 4;
        int c4  = (idx & 15) << 2;
        float4 v = *(const float4*)(aS + row * AS_ST + c4);
        *(float4*)(att + (row0 + row) * NSLOT + c4) = v;
    }

    // ========== GEMM3: m[r][c] = sum_s a[r][s] * mem[s][c] ==========
    // Packed over COLUMN PAIRS: m2[rr][cp], b-pairs load directly from memS.
    ull m2[8][4];
    #pragma unroll
    for (int rr = 0; rr < 8; rr++)
        #pragma unroll
        for (int cp = 0; cp < 4; cp++) m2[rr][cp] = 0ull;
    #pragma unroll 4
    for (int k = 0; k < NSLOT; k++) {
        ulonglong2 b0 = *(const ulonglong2*)(memS + k * MS_ST + cA);
        ulonglong2 b1 = *(const ulonglong2*)(memS + k * MS_ST + cB);
        #pragma unroll
        for (int rr = 0; rr < 8; rr++) {
            float a = aS[(r0 + rr) * AS_ST + k];
            ull ad = pack2(a, a);
            fma2(m2[rr][0], ad, b0.x); fma2(m2[rr][1], ad, b0.y);
            fma2(m2[rr][2], ad, b1.x); fma2(m2[rr][3], ad, b1.y);
        }
    }

    // store memory-read tile: to gmem output and to eS (reused as m operand)
    #pragma unroll
    for (int rr = 0; rr < 8; rr++) {
        float2 u0 = unpack2(m2[rr][0]);
        float2 u1 = unpack2(m2[rr][1]);
        float2 u2 = unpack2(m2[rr][2]);
        float2 u3 = unpack2(m2[rr][3]);
        float4 v0 = make_float4(u0.x, u0.y, u1.x, u1.y);
        float4 v1 = make_float4(u2.x, u2.y, u3.x, u3.y);
        *(float4*)(eS + (r0 + rr) * ES_ST + cA) = v0;
        *(float4*)(eS + (r0 + rr) * ES_ST + cB) = v1;
        *(float4*)(memout + (row0 + r0 + rr) * D_K + cA) = v0;
        *(float4*)(memout + (row0 + r0 + rr) * D_K + cB) = v1;
    }

    // ========== GEMM4: recon[r][d] = sum_k m[r][k] * dec_w[d][k] + dec_b[d] ==========
    // Packed over COLUMN PAIRS: b-pairs direct from Ws, a duplicated per row.
    for (int h = 0; h < 2; h++) {          // two 256-wide output halves
        ull a4[8][4];
        #pragma unroll
        for (int rr = 0; rr < 8; rr++)
            #pragma unroll
            for (int cp = 0; cp < 4; cp++) a4[rr][cp] = 0ull;

        for (int kt = 0; kt < D_K / KT; kt++) {
            __syncthreads();   // protects Ws reuse (and, on first iter, eS writes)
            #pragma unroll 8
            for (int idx = tid; idx < (256 * KT / 4); idx += NTH) {
                int c  = idx >> 3;
                int kq = idx & 7;
                float4 v = *(const float4*)(dec_w + (h * 256 + c) * D_K + kt * KT + (kq << 2));
                Ws[(kq * 4 + 0) * WS_ST + c] = v.x;
                Ws[(kq * 4 + 1) * WS_ST + c] = v.y;
                Ws[(kq * 4 + 2) * WS_ST + c] = v.z;
                Ws[(kq * 4 + 3) * WS_ST + c] = v.w;
            }
            __syncthreads();
            #pragma unroll 4
            for (int kk = 0; kk < KT; kk++) {
                ulonglong2 b0 = *(const ulonglong2*)(Ws + kk * WS_ST + cA);
                ulonglong2 b1 = *(const ulonglong2*)(Ws + kk * WS_ST + cB);
                #pragma unroll
                for (int rr = 0; rr < 8; rr++) {
                    float a = eS[(r0 + rr) * ES_ST + kt * KT + kk];
                    ull ad = pack2(a, a);
                    fma2(a4[rr][0], ad, b0.x); fma2(a4[rr][1], ad, b0.y);
                    fma2(a4[rr][2], ad, b1.x); fma2(a4[rr][3], ad, b1.y);
                }
            }
        }

        float4 db0 = *(const float4*)(dec_b + h * 256 + cA);
        float4 db1 = *(const float4*)(dec_b + h * 256 + cB);
        #pragma unroll
        for (int rr = 0; rr < 8; rr++) {
            float2 u0 = unpack2(a4[rr][0]);
            float2 u1 = unpack2(a4[rr][1]);
            float2 u2 = unpack2(a4[rr][2]);
            float2 u3 = unpack2(a4[rr][3]);
            float4 v0 = make_float4(u0.x + db0.x, u0.y + db0.y,
                                    u1.x + db0.z, u1.y + db0.w);
            float4 v1 = make_float4(u2.x + db1.x, u2.y + db1.y,
                                    u3.x + db1.z, u3.y + db1.w);
            *(float4*)(recon + (row0 + r0 + rr) * D_IN + h * 256 + cA) = v0;
            *(float4*)(recon + (row0 + r0 + rr) * D_IN + h * 256 + cB) = v1;
        }
    }
}

extern "C" void kernel_launch(void* const* d_in, const int* in_sizes, int n_in,
                              void* d_out, int out_size)
{
    const float* seq   = (const float*)d_in[0];
    const float* enc_w = (const float*)d_in[1];
    const float* enc_b = (const float*)d_in[2];
    const float* memw  = (const float*)d_in[3];
    const float* dec_w = (const float*)d_in[4];
    const float* dec_b = (const float*)d_in[5];

    const long R = (long)in_sizes[0] / D_IN;   // total rows = B*S = 65536

    float* out    = (float*)d_out;
    float* recon  = out;                        // [R, 512]
    float* att    = out + R * D_IN;             // [R, 64]
    float* memout = att + R * NSLOT;            // [R, 256]

    cudaFuncSetAttribute(mwm_fused, cudaFuncAttributeMaxDynamicSharedMemorySize, SMEM_BYTES);

    dim3 grid((unsigned)(R / TILE_R));
    mwm_fused<<<grid, NTH, SMEM_BYTES>>>(seq, enc_w, enc_b, memw, dec_w, dec_b,
                                         recon, att, memout);
}

// round 3
// speedup vs baseline: 1.0801x; 1.0542x over previous
#include <cuda_runtime.h>
#include <math.h>

// Problem constants (fixed by reference)
#define D_IN   512
#define D_K    256
#define NSLOT  64
#define TILE_R 64
#define KT     32
#define NTH    256

// Shared-memory strides (floats). Chosen so vector LDS are bank-conflict-free
// (stride ≡ 4 mod 32 for the 260 ones) and 8B-aligned pair loads work (even).
#define MS_ST 260   // memory bank [64 slots][256]
#define ES_ST 260   // encoded tile (reused for memory-read tile) [64][256]
#define AS_ST 68    // attention tile [64][64]
#define XS_ST 66    // X chunk, transposed [32 k][64 rows]  (even: pair loads)
#define WS_ST 260   // weight chunk, transposed [32 k][256 cols]

#define SMEM_FLOATS (NSLOT*MS_ST + TILE_R*ES_ST + TILE_R*AS_ST + KT*XS_ST + KT*WS_ST)
#define SMEM_BYTES  (SMEM_FLOATS * 4)

typedef unsigned long long ull;

// Packed fp32x2 FMA (Blackwell): 2 MACs per issue slot, fp32-exact per element.
__device__ __forceinline__ void fma2(ull &d, ull a, ull b) {
    asm("fma.rn.f32x2 %0, %1, %2, %0;" : "+l"(d) : "l"(a), "l"(b));
}
__device__ __forceinline__ ull pack2(float x, float y) {
    ull r;
    asm("mov.b64 %0, {%1, %2};" : "=l"(r)
        : "r"(__float_as_uint(x)), "r"(__float_as_uint(y)));
    return r;
}
__device__ __forceinline__ float2 unpack2(ull v) {
    unsigned lo, hi;
    asm("mov.b64 {%0, %1}, %2;" : "=r"(lo), "=r"(hi) : "l"(v));
    return make_float2(__uint_as_float(lo), __uint_as_float(hi));
}

__global__ __launch_bounds__(NTH, 1)
void mwm_fused(const float* __restrict__ seq,
               const float* __restrict__ enc_w,
               const float* __restrict__ enc_b,
               const float* __restrict__ memw,
               const float* __restrict__ dec_w,
               const float* __restrict__ dec_b,
               float* __restrict__ recon,
               float* __restrict__ att,
               float* __restrict__ memout)
{
    extern __shared__ float sm[];
    float* memS = sm;                       // [64][MS_ST]
    float* eS   = memS + NSLOT * MS_ST;     // [64][ES_ST]  encoded, later memory-read
    float* aS   = eS   + TILE_R * ES_ST;    // [64][AS_ST]  attention
    float* Xs   = aS   + TILE_R * AS_ST;    // [KT][XS_ST]  x chunk (transposed)
    float* Ws   = Xs   + KT * XS_ST;        // [KT][WS_ST]  weight chunk (transposed)

    const int tid = threadIdx.x;
    const int wi  = tid >> 5;          // 0..7  -> row block
    const int ln  = tid & 31;          // 0..31 -> col block
    const int r0  = wi * 8;            // 8 rows per thread
    const int cA  = ln * 4;            // cols [cA..cA+3]
    const int cB  = 128 + ln * 4;      // cols [cB..cB+3]
    const long row0 = (long)blockIdx.x * TILE_R;

    // ---- Load memory bank into smem: memS[slot][k] ----
    #pragma unroll 4
    for (int idx = tid; idx < NSLOT * (D_K / 4); idx += NTH) {
        int slot = idx >> 6;
        int c4   = (idx & 63) << 2;
        float4 v = *(const float4*)(memw + slot * D_K + c4);
        *(float4*)(memS + slot * MS_ST + c4) = v;
    }

    // ================= GEMM1: e = tanh(x @ enc_w^T + enc_b) =================
    // Accumulators packed over ROW PAIRS: acc2[p][c] = {row r0+2p, row r0+2p+1}
    ull acc2[4][8];
    #pragma unroll
    for (int p = 0; p < 4; p++)
        #pragma unroll
        for (int c = 0; c < 8; c++) acc2[p][c] = 0ull;

    for (int kt = 0; kt < D_IN / KT; kt++) {
        __syncthreads();
        // X chunk: seq[row0+row][kt*32 + k] -> Xs[k][row]
        #pragma unroll 2
        for (int idx = tid; idx < (TILE_R * KT / 4); idx += NTH) {
            int row = idx >> 3;
            int kq  = idx & 7;
            float4 v = *(const float4*)(seq + (row0 + row) * D_IN + kt * KT + (kq << 2));
            Xs[(kq * 4 + 0) * XS_ST + row] = v.x;
            Xs[(kq * 4 + 1) * XS_ST + row] = v.y;
            Xs[(kq * 4 + 2) * XS_ST + row] = v.z;
            Xs[(kq * 4 + 3) * XS_ST + row] = v.w;
        }
        // W chunk: enc_w[c][kt*32 + k] -> Ws[k][c]
        #pragma unroll 8
        for (int idx = tid; idx < (D_K * KT / 4); idx += NTH) {
            int c  = idx >> 3;
            int kq = idx & 7;
            float4 v = *(const float4*)(enc_w + c * D_IN + kt * KT + (kq << 2));
            Ws[(kq * 4 + 0) * WS_ST + c] = v.x;
            Ws[(kq * 4 + 1) * WS_ST + c] = v.y;
            Ws[(kq * 4 + 2) * WS_ST + c] = v.z;
            Ws[(kq * 4 + 3) * WS_ST + c] = v.w;
        }
        __syncthreads();
        #pragma unroll 4
        for (int kk = 0; kk < KT; kk++) {
            const float* wrow = Ws + kk * WS_ST;
            float4 b0 = *(const float4*)(wrow + cA);
            float4 b1 = *(const float4*)(wrow + cB);
            ull bb[8];
            bb[0] = pack2(b0.x, b0.x); bb[1] = pack2(b0.y, b0.y);
            bb[2] = pack2(b0.z, b0.z); bb[3] = pack2(b0.w, b0.w);
            bb[4] = pack2(b1.x, b1.x); bb[5] = pack2(b1.y, b1.y);
            bb[6] = pack2(b1.z, b1.z); bb[7] = pack2(b1.w, b1.w);
            const float* xrow = Xs + kk * XS_ST + r0;
            ull aa[4];
            aa[0] = *(const ull*)(xrow + 0);
            aa[1] = *(const ull*)(xrow + 2);
            aa[2] = *(const ull*)(xrow + 4);
            aa[3] = *(const ull*)(xrow + 6);
            #pragma unroll
            for (int p = 0; p < 4; p++)
                #pragma unroll
                for (int c = 0; c < 8; c++)
                    fma2(acc2[p][c], aa[p], bb[c]);
        }
    }

    // bias + tanh -> eS (row r0+2p from .x lane, row r0+2p+1 from .y lane)
    {
        float4 eb0 = *(const float4*)(enc_b + cA);
        float4 eb1 = *(const float4*)(enc_b + cB);
        #pragma unroll
        for (int p = 0; p < 4; p++) {
            float2 u[8];
            #pragma unroll
            for (int c = 0; c < 8; c++) u[c] = unpack2(acc2[p][c]);
            float4 vA0, vB0, vA1, vB1;
            vA0.x = tanhf(u[0].x + eb0.x); vA0.y = tanhf(u[1].x + eb0.y);
            vA0.z = tanhf(u[2].x + eb0.z); vA0.w = tanhf(u[3].x + eb0.w);
            vB0.x = tanhf(u[4].x + eb1.x); vB0.y = tanhf(u[5].x + eb1.y);
            vB0.z = tanhf(u[6].x + eb1.z); vB0.w = tanhf(u[7].x + eb1.w);
            vA1.x = tanhf(u[0].y + eb0.x); vA1.y = tanhf(u[1].y + eb0.y);
            vA1.z = tanhf(u[2].y + eb0.z); vA1.w = tanhf(u[3].y + eb0.w);
            vB1.x = tanhf(u[4].y + eb1.x); vB1.y = tanhf(u[5].y + eb1.y);
            vB1.z = tanhf(u[6].y + eb1.z); vB1.w = tanhf(u[7].y + eb1.w);
            *(float4*)(eS + (r0 + 2*p    ) * ES_ST + cA) = vA0;
            *(float4*)(eS + (r0 + 2*p    ) * ES_ST + cB) = vB0;
            *(float4*)(eS + (r0 + 2*p + 1) * ES_ST + cA) = vA1;
            *(float4*)(eS + (r0 + 2*p + 1) * ES_ST + cB) = vB1;
        }
    }
    __syncthreads();

    // ========== GEMM2: logits[r][m] = sum_k e[r][k] * mem[m][k] ==========
    // Packed over k: two half dot-products per register pair, horizontal add at end.
    ull L0[8], L1[8];
    #pragma unroll
    for (int rr = 0; rr < 8; rr++) { L0[rr] = 0ull; L1[rr] = 0ull; }
    #pragma unroll 2
    for (int k = 0; k < D_K; k += 4) {
        ulonglong2 bm0 = *(const ulonglong2*)(memS + ln * MS_ST + k);
        ulonglong2 bm1 = *(const ulonglong2*)(memS + (ln + 32) * MS_ST + k);
        #pragma unroll
        for (int rr = 0; rr < 8; rr++) {
            ulonglong2 av = *(const ulonglong2*)(eS + (r0 + rr) * ES_ST + k);
            fma2(L0[rr], av.x, bm0.x); fma2(L0[rr], av.y, bm0.y);
            fma2(L1[rr], av.x, bm1.x); fma2(L1[rr], av.y, bm1.y);
        }
    }
    float l0[8], l1[8];
    #pragma unroll
    for (int rr = 0; rr < 8; rr++) {
        float2 a = unpack2(L0[rr]); l0[rr] = a.x + a.y;
        float2 b = unpack2(L1[rr]); l1[rr] = b.x + b.y;
    }

    // ---- softmax over 64 slots (scale 1/sqrt(256) = 1/16), row in one warp ----
    const float sc = 0.0625f;
    #pragma unroll
    for (int rr = 0; rr < 8; rr++) {
        float m = fmaxf(l0[rr], l1[rr]);
        #pragma unroll
        for (int o = 16; o > 0; o >>= 1)
            m = fmaxf(m, __shfl_xor_sync(0xffffffffu, m, o));
        float e0 = __expf((l0[rr] - m) * sc);
        float e1 = __expf((l1[rr] - m) * sc);
        float s = e0 + e1;
        #pragma unroll
        for (int o = 16; o > 0; o >>= 1)
            s += __shfl_xor_sync(0xffffffffu, s, o);
        float inv = 1.0f / s;
        aS[(r0 + rr) * AS_ST + ln]      = e0 * inv;
        aS[(r0 + rr) * AS_ST + ln + 32] = e1 * inv;
    }
    __syncthreads();   // aS ready; also: everyone is past GEMM2 -> eS reusable

    // ---- write attention output (coalesced) ----
    #pragma unroll 4
    for (int idx = tid; idx < TILE_R * NSLOT / 4; idx += NTH) {
        int row = idx >> 4;
        int c4  = (idx & 15) << 2;
        float4 v = *(const float4*)(aS + row * AS_ST + c4);
        *(float4*)(att + (row0 + row) * NSLOT + c4) = v;
    }

    // ========== GEMM3: m[r][c] = sum_s a[r][s] * mem[s][c] ==========
    // Packed over COLUMN PAIRS: m2[rr][cp], b-pairs load directly from memS.
    ull m2[8][4];
    #pragma unroll
    for (int rr = 0; rr < 8; rr++)
        #pragma unroll
        for (int cp = 0; cp < 4; cp++) m2[rr][cp] = 0ull;
    #pragma unroll 4
    for (int k = 0; k < NSLOT; k++) {
        ulonglong2 b0 = *(const ulonglong2*)(memS + k * MS_ST + cA);
        ulonglong2 b1 = *(const ulonglong2*)(memS + k * MS_ST + cB);
        #pragma unroll
        for (int rr = 0; rr < 8; rr++) {
            float a = aS[(r0 + rr) * AS_ST + k];
            ull ad = pack2(a, a);
            fma2(m2[rr][0], ad, b0.x); fma2(m2[rr][1], ad, b0.y);
            fma2(m2[rr][2], ad, b1.x); fma2(m2[rr][3], ad, b1.y);
        }
    }

    // store memory-read tile: to gmem output and to eS (reused as m operand)
    #pragma unroll
    for (int rr = 0; rr < 8; rr++) {
        float2 u0 = unpack2(m2[rr][0]);
        float2 u1 = unpack2(m2[rr][1]);
        float2 u2 = unpack2(m2[rr][2]);
        float2 u3 = unpack2(m2[rr][3]);
        float4 v0 = make_float4(u0.x, u0.y, u1.x, u1.y);
        float4 v1 = make_float4(u2.x, u2.y, u3.x, u3.y);
        *(float4*)(eS + (r0 + rr) * ES_ST + cA) = v0;
        *(float4*)(eS + (r0 + rr) * ES_ST + cB) = v1;
        *(float4*)(memout + (row0 + r0 + rr) * D_K + cA) = v0;
        *(float4*)(memout + (row0 + r0 + rr) * D_K + cB) = v1;
    }

    // ========== GEMM4: recon[r][d] = sum_k m[r][k] * dec_w[d][k] + dec_b[d] ==========
    // Packed over COLUMN PAIRS: b-pairs direct from Ws, a duplicated per row.
    for (int h = 0; h < 2; h++) {          // two 256-wide output halves
        ull a4[8][4];
        #pragma unroll
        for (int rr = 0; rr < 8; rr++)
            #pragma unroll
            for (int cp = 0; cp < 4; cp++) a4[rr][cp] = 0ull;

        for (int kt = 0; kt < D_K / KT; kt++) {
            __syncthreads();   // protects Ws reuse (and, on first iter, eS writes)
            #pragma unroll 8
            for (int idx = tid; idx < (256 * KT / 4); idx += NTH) {
                int c  = idx >> 3;
                int kq = idx & 7;
                float4 v = *(const float4*)(dec_w + (h * 256 + c) * D_K + kt * KT + (kq << 2));
                Ws[(kq * 4 + 0) * WS_ST + c] = v.x;
                Ws[(kq * 4 + 1) * WS_ST + c] = v.y;
                Ws[(kq * 4 + 2) * WS_ST + c] = v.z;
                Ws[(kq * 4 + 3) * WS_ST + c] = v.w;
            }
            __syncthreads();
            #pragma unroll 4
            for (int kk = 0; kk < KT; kk++) {
                ulonglong2 b0 = *(const ulonglong2*)(Ws + kk * WS_ST + cA);
                ulonglong2 b1 = *(const ulonglong2*)(Ws + kk * WS_ST + cB);
                #pragma unroll
                for (int rr = 0; rr < 8; rr++) {
                    float a = eS[(r0 + rr) * ES_ST + kt * KT + kk];
                    ull ad = pack2(a, a);
                    fma2(a4[rr][0], ad, b0.x); fma2(a4[rr][1], ad, b0.y);
                    fma2(a4[rr][2], ad, b1.x); fma2(a4[rr][3], ad, b1.y);
                }
            }
        }

        float4 db0 = *(const float4*)(dec_b + h * 256 + cA);
        float4 db1 = *(const float4*)(dec_b + h * 256 + cB);
        #pragma unroll
        for (int rr = 0; rr < 8; rr++) {
            float2 u0 = unpack2(a4[rr][0]);
            float2 u1 = unpack2(a4[rr][1]);
            float2 u2 = unpack2(a4[rr][2]);
            float2 u3 = unpack2(a4[rr][3]);
            float4 v0 = make_float4(u0.x + db0.x, u0.y + db0.y,
                                    u1.x + db0.z, u1.y + db0.w);
            float4 v1 = make_float4(u2.x + db1.x, u2.y + db1.y,
                                    u3.x + db1.z, u3.y + db1.w);
            *(float4*)(recon + (row0 + r0 + rr) * D_IN + h * 256 + cA) = v0;
            *(float4*)(recon + (row0 + r0 + rr) * D_IN + h * 256 + cB) = v1;
        }
    }
}

extern "C" void kernel_launch(void* const* d_in, const int* in_sizes, int n_in,
                              void* d_out, int out_size)
{
    const float* seq   = (const float*)d_in[0];
    const float* enc_w = (const float*)d_in[1];
    const float* enc_b = (const float*)d_in[2];
    const float* memw  = (const float*)d_in[3];
    const float* dec_w = (const float*)d_in[4];
    const float* dec_b = (const float*)d_in[5];

    const long R = (long)in_sizes[0] / D_IN;   // total rows = B*S = 65536

    float* out    = (float*)d_out;
    float* recon  = out;                        // [R, 512]
    float* att    = out + R * D_IN;             // [R, 64]
    float* memout = att + R * NSLOT;            // [R, 256]

    cudaFuncSetAttribute(mwm_fused, cudaFuncAttributeMaxDynamicSharedMemorySize, SMEM_BYTES);

    dim3 grid((unsigned)(R / TILE_R));
    mwm_fused<<<grid, NTH, SMEM_BYTES>>>(seq, enc_w, enc_b, memw, dec_w, dec_b,
                                         recon, att, memout);
}

// round 5
// speedup vs baseline: 1.2269x; 1.1359x over previous
#include <cuda_runtime.h>
#include <cuda_bf16.h>
#include <mma.h>
#include <stdint.h>
#include <math.h>

using namespace nvcuda;

#define NTH 256
#define TMROWS 128

// ---- smem offsets (bytes) ----
#define EH_OFF   0        // [128][264] bf16
#define EL_OFF   67584
// phase-1 chunk buffers (overlap E region; dead before E written)
#define XH_OFF   0        // [128][72] bf16
#define XL_OFF   18432
#define WH_OFF   36864    // [256][72] bf16
#define WL_OFF   73728
#define STG1_OFF 143360   // [128][68] f32
#define MKH_OFF  143360   // [64][136] bf16
#define MKL_OFF  160768
#define LOG_OFF  178176   // [128][68] f32
#define ATH_OFF  0        // [128][72] bf16
#define ATL_OFF  18432
#define M3H_OFF  36864    // [64][264] bf16
#define M3L_OFF  70656
#define STG3_OFF 143360   // [128][132] f32
#define MH_OFF   0        // [128][264] bf16
#define ML_OFF   67584
#define B4H_OFF  143360   // [128][72] bf16
#define B4L_OFF  161792
#define STG4_OFF 180224   // [128][68] f32
#define SMEM_TOTAL 215040

typedef wmma::fragment<wmma::matrix_a, 16,16,16, __nv_bfloat16, wmma::row_major> FragA;
typedef wmma::fragment<wmma::matrix_b, 16,16,16, __nv_bfloat16, wmma::col_major> FragBc;
typedef wmma::fragment<wmma::matrix_b, 16,16,16, __nv_bfloat16, wmma::row_major> FragBr;
typedef wmma::fragment<wmma::accumulator, 16,16,16, float> FragC;

__device__ __forceinline__ uint32_t bfpair(float a, float b) {
    __nv_bfloat162 t = __floats2bfloat162_rn(a, b);
    return *reinterpret_cast<uint32_t*>(&t);
}
__device__ __forceinline__ void split4(const float4 v, uint2 &h, uint2 &l) {
    __nv_bfloat16 hx = __float2bfloat16(v.x), hy = __float2bfloat16(v.y);
    __nv_bfloat16 hz = __float2bfloat16(v.z), hw = __float2bfloat16(v.w);
    h.x = ((uint32_t)__bfloat16_as_ushort(hy) << 16) | (uint32_t)__bfloat16_as_ushort(hx);
    h.y = ((uint32_t)__bfloat16_as_ushort(hw) << 16) | (uint32_t)__bfloat16_as_ushort(hz);
    l.x = bfpair(v.x - __bfloat162float(hx), v.y - __bfloat162float(hy));
    l.y = bfpair(v.z - __bfloat162float(hz), v.w - __bfloat162float(hw));
}
__device__ __forceinline__ void split1(float v, uint16_t &h, uint16_t &l) {
    __nv_bfloat16 hv = __float2bfloat16(v);
    h = __bfloat16_as_ushort(hv);
    l = __bfloat16_as_ushort(__float2bfloat16(v - __bfloat162float(hv)));
}

__global__ __launch_bounds__(NTH, 1)
void mwm_wmma(const float* __restrict__ seq, const float* __restrict__ enc_w,
              const float* __restrict__ enc_b, const float* __restrict__ memw,
              const float* __restrict__ dec_w, const float* __restrict__ dec_b,
              float* __restrict__ recon, float* __restrict__ att,
              float* __restrict__ memout)
{
    extern __shared__ char smem[];
    const int tid = threadIdx.x;
    const int wid = tid >> 5;
    const int wm  = wid & 3;          // warp row 0..3
    const int wn  = wid >> 2;         // warp col 0..1
    const int rm  = wm * 32;
    const long row0 = (long)blockIdx.x * TMROWS;

    __nv_bfloat16* Eh = (__nv_bfloat16*)(smem + EH_OFF);
    __nv_bfloat16* El = (__nv_bfloat16*)(smem + EL_OFF);

    // ================= GEMM1: E = tanh(X @ enc_w^T + enc_b) =================
    {
        __nv_bfloat16* Xh = (__nv_bfloat16*)(smem + XH_OFF);
        __nv_bfloat16* Xl = (__nv_bfloat16*)(smem + XL_OFF);
        __nv_bfloat16* Wh = (__nv_bfloat16*)(smem + WH_OFF);
        __nv_bfloat16* Wl = (__nv_bfloat16*)(smem + WL_OFF);

        FragC acc[2][8];
        #pragma unroll
        for (int t = 0; t < 2; t++)
            #pragma unroll
            for (int f = 0; f < 8; f++) wmma::fill_fragment(acc[t][f], 0.0f);

        for (int kc = 0; kc < 8; kc++) {
            // X chunk [128][64]
            #pragma unroll
            for (int i = 0; i < 8; i++) {
                int idx = tid + i * NTH;
                int r = idx >> 4, c4 = (idx & 15) << 2;
                float4 v = *(const float4*)(seq + (row0 + r) * 512 + kc * 64 + c4);
                uint2 h, l; split4(v, h, l);
                *(uint2*)(Xh + r * 72 + c4) = h;
                *(uint2*)(Xl + r * 72 + c4) = l;
            }
            // enc_w chunk [256][64]
            #pragma unroll
            for (int i = 0; i < 16; i++) {
                int idx = tid + i * NTH;
                int r = idx >> 4, c4 = (idx & 15) << 2;
                float4 v = *(const float4*)(enc_w + r * 512 + kc * 64 + c4);
                uint2 h, l; split4(v, h, l);
                *(uint2*)(Wh + r * 72 + c4) = h;
                *(uint2*)(Wl + r * 72 + c4) = l;
            }
            __syncthreads();
            #pragma unroll
            for (int ks = 0; ks < 4; ks++) {
                FragA ah[2], al[2];
                #pragma unroll
                for (int t = 0; t < 2; t++) {
                    wmma::load_matrix_sync(ah[t], Xh + (rm + 16 * t) * 72 + ks * 16, 72);
                    wmma::load_matrix_sync(al[t], Xl + (rm + 16 * t) * 72 + ks * 16, 72);
                }
                #pragma unroll
                for (int f = 0; f < 8; f++) {
                    int n0 = wn * 128 + f * 16;
                    FragBc bh, bl;
                    wmma::load_matrix_sync(bh, Wh + n0 * 72 + ks * 16, 72);
                    wmma::load_matrix_sync(bl, Wl + n0 * 72 + ks * 16, 72);
                    #pragma unroll
                    for (int t = 0; t < 2; t++) {
                        wmma::mma_sync(acc[t][f], ah[t], bh, acc[t][f]);
                        wmma::mma_sync(acc[t][f], ah[t], bl, acc[t][f]);
                        wmma::mma_sync(acc[t][f], al[t], bh, acc[t][f]);
                    }
                }
            }
            __syncthreads();
        }
        // epilogue: 4 rounds through staging
        float* stg = (float*)(smem + STG1_OFF);
        for (int r4 = 0; r4 < 4; r4++) {
            #pragma unroll
            for (int t = 0; t < 2; t++)
                #pragma unroll
                for (int f = 0; f < 2; f++)
                    wmma::store_matrix_sync(stg + (rm + 16 * t) * 68 + wn * 32 + f * 16,
                                            acc[t][2 * r4 + f], 68, wmma::mem_row_major);
            __syncthreads();
            #pragma unroll
            for (int i = 0; i < 32; i++) {
                int idx = tid + i * NTH;
                int r = idx >> 6, c = idx & 63;
                int gn = (c < 32) ? (r4 * 32 + c) : (128 + r4 * 32 + (c - 32));
                float e = tanhf(stg[r * 68 + c] + __ldg(enc_b + gn));
                uint16_t h, l; split1(e, h, l);
                *(uint16_t*)(Eh + r * 264 + gn) = h;
                *(uint16_t*)(El + r * 264 + gn) = l;
            }
            __syncthreads();
        }
    }

    // ================= GEMM2: logits = E @ mem^T, softmax =================
    {
        __nv_bfloat16* MKh = (__nv_bfloat16*)(smem + MKH_OFF);
        __nv_bfloat16* MKl = (__nv_bfloat16*)(smem + MKL_OFF);
        FragC acc[2][2];
        #pragma unroll
        for (int t = 0; t < 2; t++)
            #pragma unroll
            for (int f = 0; f < 2; f++) wmma::fill_fragment(acc[t][f], 0.0f);

        for (int kh = 0; kh < 2; kh++) {
            #pragma unroll
            for (int i = 0; i < 8; i++) {
                int idx = tid + i * NTH;
                int s = idx >> 5, c4 = (idx & 31) << 2;
                float4 v = *(const float4*)(memw + s * 256 + kh * 128 + c4);
                uint2 h, l; split4(v, h, l);
                *(uint2*)(MKh + s * 136 + c4) = h;
                *(uint2*)(MKl + s * 136 + c4) = l;
            }
            __syncthreads();
            #pragma unroll
            for (int ks = 0; ks < 8; ks++) {
                FragA ah[2], al[2];
                #pragma unroll
                for (int t = 0; t < 2; t++) {
                    wmma::load_matrix_sync(ah[t], Eh + (rm + 16 * t) * 264 + kh * 128 + ks * 16, 264);
                    wmma::load_matrix_sync(al[t], El + (rm + 16 * t) * 264 + kh * 128 + ks * 16, 264);
                }
                #pragma unroll
                for (int f = 0; f < 2; f++) {
                    int n0 = wn * 32 + f * 16;
                    FragBc bh, bl;
                    wmma::load_matrix_sync(bh, MKh + n0 * 136 + ks * 16, 136);
                    wmma::load_matrix_sync(bl, MKl + n0 * 136 + ks * 16, 136);
                    #pragma unroll
                    for (int t = 0; t < 2; t++) {
                        wmma::mma_sync(acc[t][f], ah[t], bh, acc[t][f]);
                        wmma::mma_sync(acc[t][f], ah[t], bl, acc[t][f]);
                        wmma::mma_sync(acc[t][f], al[t], bh, acc[t][f]);
                    }
                }
            }
            __syncthreads();
        }
        float* logit = (float*)(smem + LOG_OFF);
        #pragma unroll
        for (int t = 0; t < 2; t++)
            #pragma unroll
            for (int f = 0; f < 2; f++)
                wmma::store_matrix_sync(logit + (rm + 16 * t) * 68 + wn * 32 + f * 16,
                                        acc[t][f], 68, wmma::mem_row_major);
        __syncthreads();
        // softmax: one thread per row (threads 0-127)
        __nv_bfloat16* Ah = (__nv_bfloat16*)(smem + ATH_OFF);
        __nv_bfloat16* Al = (__nv_bfloat16*)(smem + ATL_OFF);
        if (tid < 128) {
            const float* lr = logit + tid * 68;
            float m = -1e30f;
            #pragma unroll
            for (int c = 0; c < 64; c++) m = fmaxf(m, lr[c]);
            float e[64], sum = 0.f;
            #pragma unroll
            for (int c = 0; c < 64; c++) { e[c] = __expf((lr[c] - m) * 0.0625f); sum += e[c]; }
            float inv = 1.0f / sum;
            float* arow = att + (row0 + tid) * 64;
            #pragma unroll
            for (int c = 0; c < 64; c += 4) {
                float4 v = make_float4(e[c]*inv, e[c+1]*inv, e[c+2]*inv, e[c+3]*inv);
                *(float4*)(arow + c) = v;
                uint16_t h, l;
                split1(v.x, h, l); Ah[tid*72 + c]   = __ushort_as_bfloat16(h); Al[tid*72 + c]   = __ushort_as_bfloat16(l);
                split1(v.y, h, l); Ah[tid*72 + c+1] = __ushort_as_bfloat16(h); Al[tid*72 + c+1] = __ushort_as_bfloat16(l);
                split1(v.z, h, l); Ah[tid*72 + c+2] = __ushort_as_bfloat16(h); Al[tid*72 + c+2] = __ushort_as_bfloat16(l);
                split1(v.w, h, l); Ah[tid*72 + c+3] = __ushort_as_bfloat16(h); Al[tid*72 + c+3] = __ushort_as_bfloat16(l);
            }
        }
        __syncthreads();
    }

    // ================= GEMM3: M = attn @ mem =================
    {
        __nv_bfloat16* Ah  = (__nv_bfloat16*)(smem + ATH_OFF);
        __nv_bfloat16* Al  = (__nv_bfloat16*)(smem + ATL_OFF);
        __nv_bfloat16* M3h = (__nv_bfloat16*)(smem + M3H_OFF);
        __nv_bfloat16* M3l = (__nv_bfloat16*)(smem + M3L_OFF);
        #pragma unroll
        for (int i = 0; i < 16; i++) {
            int idx = tid + i * NTH;
            int s = idx >> 6, c4 = (idx & 63) << 2;
            float4 v = *(const float4*)(memw + s * 256 + c4);
            uint2 h, l; split4(v, h, l);
            *(uint2*)(M3h + s * 264 + c4) = h;
            *(uint2*)(M3l + s * 264 + c4) = l;
        }
        __syncthreads();
        FragC acc[2][8];
        #pragma unroll
        for (int t = 0; t < 2; t++)
            #pragma unroll
            for (int f = 0; f < 8; f++) wmma::fill_fragment(acc[t][f], 0.0f);
        #pragma unroll
        for (int ks = 0; ks < 4; ks++) {
            FragA ah[2], al[2];
            #pragma unroll
            for (int t = 0; t < 2; t++) {
                wmma::load_matrix_sync(ah[t], Ah + (rm + 16 * t) * 72 + ks * 16, 72);
                wmma::load_matrix_sync(al[t], Al + (rm + 16 * t) * 72 + ks * 16, 72);
            }
            #pragma unroll
            for (int f = 0; f < 8; f++) {
                int n0 = wn * 128 + f * 16;
                FragBr bh, bl;
                wmma::load_matrix_sync(bh, M3h + ks * 16 * 264 + n0, 264);
                wmma::load_matrix_sync(bl, M3l + ks * 16 * 264 + n0, 264);
                #pragma unroll
                for (int t = 0; t < 2; t++) {
                    wmma::mma_sync(acc[t][f], ah[t], bh, acc[t][f]);
                    wmma::mma_sync(acc[t][f], ah[t], bl, acc[t][f]);
                    wmma::mma_sync(acc[t][f], al[t], bh, acc[t][f]);
                }
            }
        }
        __syncthreads();   // attn/mem3 dead; M region reuse below
        __nv_bfloat16* Mh = (__nv_bfloat16*)(smem + MH_OFF);
        __nv_bfloat16* Ml = (__nv_bfloat16*)(smem + ML_OFF);
        float* stg = (float*)(smem + STG3_OFF);
        for (int r2 = 0; r2 < 2; r2++) {
            #pragma unroll
            for (int t = 0; t < 2; t++)
                #pragma unroll
                for (int f = 0; f < 4; f++)
                    wmma::store_matrix_sync(stg + (rm + 16 * t) * 132 + wn * 64 + f * 16,
                                            acc[t][4 * r2 + f], 132, wmma::mem_row_major);
            __syncthreads();
            #pragma unroll
            for (int i = 0; i < 64; i++) {
                int idx = tid + i * NTH;
                int r = idx >> 7, c = idx & 127;
                int gn = (c < 64) ? (r2 * 64 + c) : (128 + r2 * 64 + (c - 64));
                float v = stg[r * 132 + c];
                memout[(row0 + r) * 256 + gn] = v;
                uint16_t h, l; split1(v, h, l);
                *(uint16_t*)(Mh + r * 264 + gn) = h;
                *(uint16_t*)(Ml + r * 264 + gn) = l;
            }
            __syncthreads();
        }
    }

    // ================= GEMM4: recon = M @ dec_w^T + dec_b =================
    {
        __nv_bfloat16* Mh  = (__nv_bfloat16*)(smem + MH_OFF);
        __nv_bfloat16* Ml  = (__nv_bfloat16*)(smem + ML_OFF);
        __nv_bfloat16* B4h = (__nv_bfloat16*)(smem + B4H_OFF);
        __nv_bfloat16* B4l = (__nv_bfloat16*)(smem + B4L_OFF);
        float* stg = (float*)(smem + STG4_OFF);
        for (int nt = 0; nt < 4; nt++) {
            FragC acc[2][4];
            #pragma unroll
            for (int t = 0; t < 2; t++)
                #pragma unroll
                for (int f = 0; f < 4; f++) wmma::fill_fragment(acc[t][f], 0.0f);
            for (int kc = 0; kc < 4; kc++) {
                #pragma unroll
                for (int i = 0; i < 8; i++) {
                    int idx = tid + i * NTH;
                    int n = idx >> 4, c4 = (idx & 15) << 2;
                    float4 v = *(const float4*)(dec_w + (nt * 128 + n) * 256 + kc * 64 + c4);
                    uint2 h, l; split4(v, h, l);
                    *(uint2*)(B4h + n * 72 + c4) = h;
                    *(uint2*)(B4l + n * 72 + c4) = l;
                }
                __syncthreads();
                #pragma unroll
                for (int ks = 0; ks < 4; ks++) {
                    FragA ah[2], al[2];
                    #pragma unroll
                    for (int t = 0; t < 2; t++) {
                        wmma::load_matrix_sync(ah[t], Mh + (rm + 16 * t) * 264 + kc * 64 + ks * 16, 264);
                        wmma::load_matrix_sync(al[t], Ml + (rm + 16 * t) * 264 + kc * 64 + ks * 16, 264);
                    }
                    #pragma unroll
                    for (int f = 0; f < 4; f++) {
                        int n0 = wn * 64 + f * 16;
                        FragBc bh, bl;
                        wmma::load_matrix_sync(bh, B4h + n0 * 72 + ks * 16, 72);
                        wmma::load_matrix_sync(bl, B4l + n0 * 72 + ks * 16, 72);
                        #pragma unroll
                        for (int t = 0; t < 2; t++) {
                            wmma::mma_sync(acc[t][f], ah[t], bh, acc[t][f]);
                            wmma::mma_sync(acc[t][f], ah[t], bl, acc[t][f]);
                            wmma::mma_sync(acc[t][f], al[t], bh, acc[t][f]);
                        }
                    }
                }
                __syncthreads();
            }
            for (int r2 = 0; r2 < 2; r2++) {
                #pragma unroll
                for (int t = 0; t < 2; t++)
                    #pragma unroll
                    for (int f = 0; f < 2; f++)
                        wmma::store_matrix_sync(stg + (rm + 16 * t) * 68 + wn * 32 + f * 16,
                                                acc[t][2 * r2 + f], 68, wmma::mem_row_major);
                __syncthreads();
                #pragma unroll
                for (int i = 0; i < 32; i++) {
                    int idx = tid + i * NTH;
                    int r = idx >> 6, c = idx & 63;
                    int gnl = (c < 32) ? (r2 * 32 + c) : (64 + r2 * 32 + (c - 32));
                    int d = nt * 128 + gnl;
                    recon[(row0 + r) * 512 + d] = stg[r * 68 + c] + __ldg(dec_b + d);
                }
                __syncthreads();
            }
        }
    }
}

extern "C" void kernel_launch(void* const* d_in, const int* in_sizes, int n_in,
                              void* d_out, int out_size)
{
    const float* seq   = (const float*)d_in[0];
    const float* enc_w = (const float*)d_in[1];
    const float* enc_b = (const float*)d_in[2];
    const float* memw  = (const float*)d_in[3];
    const float* dec_w = (const float*)d_in[4];
    const float* dec_b = (const float*)d_in[5];

    const long R = (long)in_sizes[0] / 512;   // B*S = 65536

    float* out    = (float*)d_out;
    float* recon  = out;
    float* att    = out + R * 512;
    float* memout = att + R * 64;

    cudaFuncSetAttribute(mwm_wmma, cudaFuncAttributeMaxDynamicSharedMemorySize, SMEM_TOTAL);
    mwm_wmma<<<(unsigned)(R / TMROWS), NTH, SMEM_TOTAL>>>(seq, enc_w, enc_b, memw,
                                                          dec_w, dec_b, recon, att, memout);
}